// round 16
// baseline (speedup 1.0000x reference)
#include <cuda_runtime.h>
#include <cuda_bf16.h>
#include <cuda_fp16.h>
#include <cstdint>

#define DOUT 128
#define NCAP 50048
#define LDA 136            // padded smem row stride in bf16 elems (272 B)
#define SEG_BLOCKS 48

// Scratch (device globals — allocation-free rule)
__device__ __half   g_hh[(size_t)NCAP * DOUT];   // h in fp16 (12.8 MB, L2-resident)
__device__ float    g_sdst[NCAP];
__device__ float    g_ssrc[NCAP];
__device__ int      g_seg[NCAP + 1];

__device__ __forceinline__ uint32_t smem_u32(const void* p) {
    uint32_t a;
    asm("{ .reg .u64 t; cvta.to.shared.u64 t, %1; cvt.u32.u64 %0, t; }" : "=r"(a) : "l"(p));
    return a;
}

__device__ __forceinline__ void ldsm_x4(uint32_t* r, uint32_t addr) {
    asm volatile("ldmatrix.sync.aligned.m8n8.x4.shared.b16 {%0,%1,%2,%3}, [%4];"
                 : "=r"(r[0]), "=r"(r[1]), "=r"(r[2]), "=r"(r[3]) : "r"(addr));
}

__device__ __forceinline__ void ldsm_x4_trans(uint32_t* r, uint32_t addr) {
    asm volatile("ldmatrix.sync.aligned.m8n8.x4.trans.shared.b16 {%0,%1,%2,%3}, [%4];"
                 : "=r"(r[0]), "=r"(r[1]), "=r"(r[2]), "=r"(r[3]) : "r"(addr));
}

__device__ __forceinline__ void mma_bf16(float* c, const uint32_t* a, const uint32_t* b) {
    asm volatile(
        "mma.sync.aligned.m16n8k16.row.col.f32.bf16.bf16.f32 "
        "{%0,%1,%2,%3}, {%4,%5,%6,%7}, {%8,%9}, {%0,%1,%2,%3};"
        : "+f"(c[0]), "+f"(c[1]), "+f"(c[2]), "+f"(c[3])
        : "r"(a[0]), "r"(a[1]), "r"(a[2]), "r"(a[3]), "r"(b[0]), "r"(b[1]));
}

// ---------------------------------------------------------------------------
// Seg build (device fn): runs inside the GEMM kernel's trailing blocks.
// ---------------------------------------------------------------------------
__device__ void seg_build(const int* __restrict__ edst, int N, int E, int blk) {
    const int tid = threadIdx.x;
    const int nchunk = (E + 3) >> 2;
    const int stride = SEG_BLOCKS * 512;
    for (int t = blk * 512 + tid; t < nchunk; t += stride) {
        int base = t * 4;
        int4 d4;
        if (base + 3 < E) {
            d4 = *(const int4*)&edst[base];
        } else {
            d4.x = __ldg(&edst[base]);
            d4.y = (base + 1 < E) ? __ldg(&edst[base + 1]) : d4.x;
            d4.z = (base + 2 < E) ? __ldg(&edst[base + 2]) : d4.y;
            d4.w = (base + 3 < E) ? __ldg(&edst[base + 3]) : d4.z;
        }
        int dm1 = __shfl_up_sync(0xffffffffu, d4.w, 1);
        if ((tid & 31) == 0)
            dm1 = (base == 0) ? -1 : __ldg(&edst[base - 1]);

        if (d4.x > dm1)  for (int n = dm1 + 1;  n <= d4.x; n++) g_seg[n] = base;
        if (base + 1 < E && d4.y > d4.x) for (int n = d4.x + 1; n <= d4.y; n++) g_seg[n] = base + 1;
        if (base + 2 < E && d4.z > d4.y) for (int n = d4.y + 1; n <= d4.z; n++) g_seg[n] = base + 2;
        if (base + 3 < E && d4.w > d4.z) for (int n = d4.z + 1; n <= d4.w; n++) g_seg[n] = base + 3;
        if (base + 4 >= E) {
            for (int n = d4.w + 1; n <= N; n++) g_seg[n] = E;
        }
    }
}

// ---------------------------------------------------------------------------
// Kernel 1: bf16-split tensor GEMM (round-13 winner, unchanged).
// ---------------------------------------------------------------------------
static const uint32_t A_HI = 0;
static const uint32_t A_LO = 34816;
static const uint32_t B_HI = 69632;
static const uint32_t B_LO = 104448;
static const uint32_t SC_AW = 139264;
static const uint32_t SC_B  = 140288;
static const uint32_t S_PD  = 140800;
static const uint32_t S_PS  = 142848;
static const uint32_t GEMM_SMEM = 144896;

__global__ void __launch_bounds__(512, 1)
gat_gemm_mma_kernel(const float* __restrict__ x, const float* __restrict__ W,
                    const float* __restrict__ b, const float* __restrict__ aw,
                    const int* __restrict__ edst,
                    int N, int E, int gemm_blocks) {
    if ((int)blockIdx.x >= gemm_blocks) {
        seg_build(edst, N, E, blockIdx.x - gemm_blocks);
        return;
    }

    extern __shared__ char smem[];
    const uint32_t sb = smem_u32(smem);
    const int tid = threadIdx.x, wid = tid >> 5, lane = tid & 31;
    const int warp_m = wid >> 2, warp_n = wid & 3;
    const int m0 = warp_m * 32, n0 = warp_n * 32;
    const int row0 = blockIdx.x * 128;

    if (tid < 256) ((float*)(smem + SC_AW))[tid] = aw[tid];
    else if (tid < 384) ((float*)(smem + SC_B))[tid - 256] = b[tid - 256];

#pragma unroll
    for (int i = 0; i < 8; i++) {
        int j = tid + i * 512;
        int k = j >> 5;
        int n = (j & 31) * 4;
        float4 v = *(const float4*)&W[(size_t)k * 128 + n];
        __nv_bfloat162 h01 = __floats2bfloat162_rn(v.x, v.y);
        __nv_bfloat162 h23 = __floats2bfloat162_rn(v.z, v.w);
        float l0 = v.x - __bfloat162float(h01.x);
        float l1 = v.y - __bfloat162float(h01.y);
        float l2 = v.z - __bfloat162float(h23.x);
        float l3 = v.w - __bfloat162float(h23.y);
        __nv_bfloat162 lo01 = __floats2bfloat162_rn(l0, l1);
        __nv_bfloat162 lo23 = __floats2bfloat162_rn(l2, l3);
        uint32_t off = (uint32_t)(k * LDA + n) * 2;
        *(uint2*)(smem + B_HI + off) = make_uint2(*(uint32_t*)&h01, *(uint32_t*)&h23);
        *(uint2*)(smem + B_LO + off) = make_uint2(*(uint32_t*)&lo01, *(uint32_t*)&lo23);
    }

#pragma unroll
    for (int i = 0; i < 8; i++) {
        int j = tid + i * 512;
        int row = j >> 5;
        int c = (j & 31) * 4;
        float4 v = make_float4(0.f, 0.f, 0.f, 0.f);
        int gr = row0 + row;
        if (gr < N) v = *(const float4*)&x[(size_t)gr * 128 + c];
        __nv_bfloat162 h01 = __floats2bfloat162_rn(v.x, v.y);
        __nv_bfloat162 h23 = __floats2bfloat162_rn(v.z, v.w);
        float l0 = v.x - __bfloat162float(h01.x);
        float l1 = v.y - __bfloat162float(h01.y);
        float l2 = v.z - __bfloat162float(h23.x);
        float l3 = v.w - __bfloat162float(h23.y);
        __nv_bfloat162 lo01 = __floats2bfloat162_rn(l0, l1);
        __nv_bfloat162 lo23 = __floats2bfloat162_rn(l2, l3);
        uint32_t off = (uint32_t)(row * LDA + c) * 2;
        *(uint2*)(smem + A_HI + off) = make_uint2(*(uint32_t*)&h01, *(uint32_t*)&h23);
        *(uint2*)(smem + A_LO + off) = make_uint2(*(uint32_t*)&lo01, *(uint32_t*)&lo23);
    }
    __syncthreads();

    float acc[2][4][4];
#pragma unroll
    for (int mb = 0; mb < 2; mb++)
#pragma unroll
        for (int nb = 0; nb < 4; nb++)
#pragma unroll
            for (int q = 0; q < 4; q++) acc[mb][nb][q] = 0.f;

    const int a_row = lane & 15, a_half = (lane >> 4) * 8;

#pragma unroll
    for (int ks = 0; ks < 8; ks++) {
        int k0 = ks * 16;
        uint32_t ahi[2][4], alo[2][4], bhi[4][2], blo[4][2];
#pragma unroll
        for (int mb = 0; mb < 2; mb++) {
            uint32_t aoff = (uint32_t)((m0 + mb * 16 + a_row) * LDA + k0 + a_half) * 2;
            ldsm_x4(ahi[mb], sb + A_HI + aoff);
            ldsm_x4(alo[mb], sb + A_LO + aoff);
        }
#pragma unroll
        for (int p = 0; p < 2; p++) {
            uint32_t boff =
                (uint32_t)((k0 + a_row) * LDA + n0 + p * 16 + a_half) * 2;
            uint32_t r[4];
            ldsm_x4_trans(r, sb + B_HI + boff);
            bhi[2 * p][0] = r[0]; bhi[2 * p][1] = r[1];
            bhi[2 * p + 1][0] = r[2]; bhi[2 * p + 1][1] = r[3];
            ldsm_x4_trans(r, sb + B_LO + boff);
            blo[2 * p][0] = r[0]; blo[2 * p][1] = r[1];
            blo[2 * p + 1][0] = r[2]; blo[2 * p + 1][1] = r[3];
        }
#pragma unroll
        for (int mb = 0; mb < 2; mb++)
#pragma unroll
            for (int nb = 0; nb < 4; nb++)
                mma_bf16(acc[mb][nb], ahi[mb], bhi[nb]);
#pragma unroll
        for (int mb = 0; mb < 2; mb++)
#pragma unroll
            for (int nb = 0; nb < 4; nb++)
                mma_bf16(acc[mb][nb], ahi[mb], blo[nb]);
#pragma unroll
        for (int mb = 0; mb < 2; mb++)
#pragma unroll
            for (int nb = 0; nb < 4; nb++)
                mma_bf16(acc[mb][nb], alo[mb], bhi[nb]);
    }

    const float* s_awd = (const float*)(smem + SC_AW);
    const float* s_aws = s_awd + 128;
    const float* s_bb  = (const float*)(smem + SC_B);
    float pd4[4] = {0.f, 0.f, 0.f, 0.f};
    float ps4[4] = {0.f, 0.f, 0.f, 0.f};

#pragma unroll
    for (int mb = 0; mb < 2; mb++) {
        int gr0 = row0 + m0 + mb * 16 + (lane >> 2);
        int gr1 = gr0 + 8;
#pragma unroll
        for (int nb = 0; nb < 4; nb++) {
            int col = n0 + nb * 8 + (lane & 3) * 2;
            float bc0 = s_bb[col], bc1 = s_bb[col + 1];
            float v00 = acc[mb][nb][0] + bc0;
            float v01 = acc[mb][nb][1] + bc1;
            float v10 = acc[mb][nb][2] + bc0;
            float v11 = acc[mb][nb][3] + bc1;
            float ad0 = s_awd[col], ad1 = s_awd[col + 1];
            float as0 = s_aws[col], as1 = s_aws[col + 1];
            pd4[mb * 2 + 0] = fmaf(v00, ad0, fmaf(v01, ad1, pd4[mb * 2 + 0]));
            pd4[mb * 2 + 1] = fmaf(v10, ad0, fmaf(v11, ad1, pd4[mb * 2 + 1]));
            ps4[mb * 2 + 0] = fmaf(v00, as0, fmaf(v01, as1, ps4[mb * 2 + 0]));
            ps4[mb * 2 + 1] = fmaf(v10, as0, fmaf(v11, as1, ps4[mb * 2 + 1]));
            if (gr0 < N) {
                __half2 hp = __floats2half2_rn(v00, v01);
                *(uint32_t*)&g_hh[(size_t)gr0 * 128 + col] = *(uint32_t*)&hp;
            }
            if (gr1 < N) {
                __half2 hp = __floats2half2_rn(v10, v11);
                *(uint32_t*)&g_hh[(size_t)gr1 * 128 + col] = *(uint32_t*)&hp;
            }
        }
    }

#pragma unroll
    for (int q = 0; q < 4; q++) {
        pd4[q] += __shfl_xor_sync(0xffffffffu, pd4[q], 1);
        pd4[q] += __shfl_xor_sync(0xffffffffu, pd4[q], 2);
        ps4[q] += __shfl_xor_sync(0xffffffffu, ps4[q], 1);
        ps4[q] += __shfl_xor_sync(0xffffffffu, ps4[q], 2);
    }
    float* sPD = (float*)(smem + S_PD);
    float* sPS = (float*)(smem + S_PS);
    if ((lane & 3) == 0) {
#pragma unroll
        for (int q = 0; q < 4; q++) {
            int r = m0 + (q >> 1) * 16 + (q & 1) * 8 + (lane >> 2);
            sPD[warp_n * 128 + r] = pd4[q];
            sPS[warp_n * 128 + r] = ps4[q];
        }
    }
    __syncthreads();
    if (tid < 128) {
        int gr = row0 + tid;
        if (gr < N) {
            g_sdst[gr] = (sPD[tid] + sPD[128 + tid]) + (sPD[256 + tid] + sPD[384 + tid]);
            g_ssrc[gr] = (sPS[tid] + sPS[128 + tid]) + (sPS[256 + tid] + sPS[384 + tid]);
        }
    }
}

// ---------------------------------------------------------------------------
// Agg helper: generic chunked path for one node (deg > 32 fallback).
// ---------------------------------------------------------------------------
__device__ __forceinline__ void agg_one(const int* __restrict__ esrc,
                                        int ss, int ee, float sdn, float ab,
                                        float2* wb, int lane,
                                        float4& acc, float& denom) {
    const char* hbase = (const char*)g_hh + lane * 8;
    for (int base = ss; base < ee; base += 32) {
        int e = base + lane;
        int off = 0;
        float w = 0.f;
        if (e < ee) {
            int src = __ldg(&esrc[e]);
            float l = sdn + __ldg(&g_ssrc[src]) + ab;
            l = (l >= 0.f) ? l : 0.01f * l;
            w = __expf(l);
            denom += w;
            off = src << 8;
        }
        __syncwarp();
        wb[lane] = make_float2(w, __int_as_float(off));
        __syncwarp();
        int cnt = min(32, ee - base);
#pragma unroll 4
        for (int j = 0; j < cnt; j++) {
            float2 p = wb[j];
            uint2 u = *(const uint2*)(hbase + __float_as_int(p.y));
            float2 f0 = __half22float2(*(__half2*)&u.x);
            float2 f1 = __half22float2(*(__half2*)&u.y);
            acc.x = fmaf(p.x, f0.x, acc.x);
            acc.y = fmaf(p.x, f0.y, acc.y);
            acc.z = fmaf(p.x, f1.x, acc.z);
            acc.w = fmaf(p.x, f1.y, acc.w);
        }
        __syncwarp();
    }
}

// ---------------------------------------------------------------------------
// Kernel 2: softmax + aggregation, TWO adjacent nodes per warp.
// Fused j-loop over max(d0,d1) with 2 independent gather chains per trip.
// No max subtraction (logits O(1); exp(l)/sum exp(l) exact).
// ---------------------------------------------------------------------------
__global__ void __launch_bounds__(256)
gat_agg_kernel(const int* __restrict__ esrc,
               const float* __restrict__ abp, float* __restrict__ out, int N) {
    __shared__ float2 wbuf_all[8][64];   // per warp: [0..31] node0, [32..63] node1

    const int warp = threadIdx.x >> 5;
    const int lane = threadIdx.x & 31;
    const int n0 = (blockIdx.x * 8 + warp) * 2;
    if (n0 >= N) return;
    const int n1 = n0 + 1;
    const bool has1 = (n1 < N);
    const float ab = __ldg(abp);

    const int s0 = __ldg(&g_seg[n0]);
    const int e0 = __ldg(&g_seg[n0 + 1]);
    const int e1 = has1 ? __ldg(&g_seg[n0 + 2]) : e0;
    const int d0 = e0 - s0, d1 = e1 - e0;

    const float sdn0 = __ldg(&g_sdst[n0]);
    const float sdn1 = has1 ? __ldg(&g_sdst[n1]) : 0.f;
    float2* wbuf = wbuf_all[warp];
    const char* hbase = (const char*)g_hh + lane * 8;

    float4 acc0 = make_float4(0.f, 0.f, 0.f, 0.f);
    float4 acc1 = make_float4(0.f, 0.f, 0.f, 0.f);
    float denom0 = 0.f, denom1 = 0.f;

    if (d0 <= 32 && d1 <= 32) {
        // Fast path: both prefixes concurrently, fused interleaved j-loop.
        int eA = s0 + lane;
        int off0 = 0;
        float w0 = 0.f;
        if (eA < e0) {
            int src = __ldg(&esrc[eA]);
            float l = sdn0 + __ldg(&g_ssrc[src]) + ab;
            l = (l >= 0.f) ? l : 0.01f * l;
            w0 = __expf(l);
            off0 = src << 8;
        }
        int eB = e0 + lane;
        int off1 = 0;
        float w1 = 0.f;
        if (eB < e1) {
            int src = __ldg(&esrc[eB]);
            float l = sdn1 + __ldg(&g_ssrc[src]) + ab;
            l = (l >= 0.f) ? l : 0.01f * l;
            w1 = __expf(l);
            off1 = src << 8;
        }
        denom0 = w0;
        denom1 = w1;
        wbuf[lane]      = make_float2(w0, __int_as_float(off0));
        wbuf[32 + lane] = make_float2(w1, __int_as_float(off1));
        __syncwarp();

        int dmax = max(d0, d1);
#pragma unroll 4
        for (int j = 0; j < dmax; j++) {
            if (j < d0) {
                float2 p = wbuf[j];
                uint2 u = *(const uint2*)(hbase + __float_as_int(p.y));
                float2 f0 = __half22float2(*(__half2*)&u.x);
                float2 f1 = __half22float2(*(__half2*)&u.y);
                acc0.x = fmaf(p.x, f0.x, acc0.x);
                acc0.y = fmaf(p.x, f0.y, acc0.y);
                acc0.z = fmaf(p.x, f1.x, acc0.z);
                acc0.w = fmaf(p.x, f1.y, acc0.w);
            }
            if (j < d1) {
                float2 p = wbuf[32 + j];
                uint2 u = *(const uint2*)(hbase + __float_as_int(p.y));
                float2 f0 = __half22float2(*(__half2*)&u.x);
                float2 f1 = __half22float2(*(__half2*)&u.y);
                acc1.x = fmaf(p.x, f0.x, acc1.x);
                acc1.y = fmaf(p.x, f0.y, acc1.y);
                acc1.z = fmaf(p.x, f1.x, acc1.z);
                acc1.w = fmaf(p.x, f1.y, acc1.w);
            }
        }
    } else {
        agg_one(esrc, s0, e0, sdn0, ab, wbuf, lane, acc0, denom0);
        if (has1)
            agg_one(esrc, e0, e1, sdn1, ab, wbuf, lane, acc1, denom1);
    }

#pragma unroll
    for (int off = 16; off; off >>= 1) {
        denom0 += __shfl_xor_sync(0xffffffffu, denom0, off);
        denom1 += __shfl_xor_sync(0xffffffffu, denom1, off);
    }
    float inv0 = (denom0 > 0.f) ? (1.f / denom0) : 0.f;
    float inv1 = (denom1 > 0.f) ? (1.f / denom1) : 0.f;
    acc0.x *= inv0; acc0.y *= inv0; acc0.z *= inv0; acc0.w *= inv0;
    acc1.x *= inv1; acc1.y *= inv1; acc1.z *= inv1; acc1.w *= inv1;
    *(float4*)&out[(size_t)n0 * 128 + lane * 4] = acc0;
    if (has1)
        *(float4*)&out[(size_t)n1 * 128 + lane * 4] = acc1;
}

// ---------------------------------------------------------------------------
extern "C" void kernel_launch(void* const* d_in, const int* in_sizes, int n_in,
                              void* d_out, int out_size) {
    const float* x    = (const float*)d_in[0];
    const int*   esrc = (const int*)d_in[1];
    const int*   edst = (const int*)d_in[2];
    const float* W    = (const float*)d_in[3];
    const float* b    = (const float*)d_in[4];
    const float* aw   = (const float*)d_in[5];
    const float* ab   = (const float*)d_in[6];
    float* out = (float*)d_out;

    const int N = in_sizes[0] / DOUT;
    const int E = in_sizes[1];

    cudaFuncSetAttribute(gat_gemm_mma_kernel,
                         cudaFuncAttributeMaxDynamicSharedMemorySize, GEMM_SMEM);
    int gemm_blocks = (N + 127) / 128;
    gat_gemm_mma_kernel<<<gemm_blocks + SEG_BLOCKS, 512, GEMM_SMEM>>>(
        x, W, b, aw, edst, N, E, gemm_blocks);

    int npairs = (N + 1) / 2;
    int agg_blocks = (npairs + 7) / 8;
    gat_agg_kernel<<<agg_blocks, 256>>>(esrc, ab, out, N);
}

// round 17
// speedup vs baseline: 1.0056x; 1.0056x over previous
#include <cuda_runtime.h>
#include <cuda_bf16.h>
#include <cuda_fp16.h>
#include <cstdint>

#define DOUT 128
#define NCAP 50048
#define LDA 136            // padded smem row stride in bf16 elems (272 B)
#define SEG_BLOCKS 48

// Scratch (device globals — allocation-free rule)
__device__ __half   g_hh[(size_t)NCAP * DOUT];   // h in fp16 (12.8 MB, L2-resident)
__device__ float    g_sdst[NCAP];
__device__ float    g_ssrc[NCAP];
__device__ int      g_seg[NCAP + 1];

__device__ __forceinline__ uint32_t smem_u32(const void* p) {
    uint32_t a;
    asm("{ .reg .u64 t; cvta.to.shared.u64 t, %1; cvt.u32.u64 %0, t; }" : "=r"(a) : "l"(p));
    return a;
}

__device__ __forceinline__ void ldsm_x4(uint32_t* r, uint32_t addr) {
    asm volatile("ldmatrix.sync.aligned.m8n8.x4.shared.b16 {%0,%1,%2,%3}, [%4];"
                 : "=r"(r[0]), "=r"(r[1]), "=r"(r[2]), "=r"(r[3]) : "r"(addr));
}

__device__ __forceinline__ void ldsm_x4_trans(uint32_t* r, uint32_t addr) {
    asm volatile("ldmatrix.sync.aligned.m8n8.x4.trans.shared.b16 {%0,%1,%2,%3}, [%4];"
                 : "=r"(r[0]), "=r"(r[1]), "=r"(r[2]), "=r"(r[3]) : "r"(addr));
}

__device__ __forceinline__ void mma_bf16(float* c, const uint32_t* a, const uint32_t* b) {
    asm volatile(
        "mma.sync.aligned.m16n8k16.row.col.f32.bf16.bf16.f32 "
        "{%0,%1,%2,%3}, {%4,%5,%6,%7}, {%8,%9}, {%0,%1,%2,%3};"
        : "+f"(c[0]), "+f"(c[1]), "+f"(c[2]), "+f"(c[3])
        : "r"(a[0]), "r"(a[1]), "r"(a[2]), "r"(a[3]), "r"(b[0]), "r"(b[1]));
}

// ---------------------------------------------------------------------------
// Seg build (device fn): runs inside the GEMM kernel's trailing blocks.
// ---------------------------------------------------------------------------
__device__ void seg_build(const int* __restrict__ edst, int N, int E, int blk) {
    const int tid = threadIdx.x;
    const int nchunk = (E + 3) >> 2;
    const int stride = SEG_BLOCKS * 512;
    for (int t = blk * 512 + tid; t < nchunk; t += stride) {
        int base = t * 4;
        int4 d4;
        if (base + 3 < E) {
            d4 = *(const int4*)&edst[base];
        } else {
            d4.x = __ldg(&edst[base]);
            d4.y = (base + 1 < E) ? __ldg(&edst[base + 1]) : d4.x;
            d4.z = (base + 2 < E) ? __ldg(&edst[base + 2]) : d4.y;
            d4.w = (base + 3 < E) ? __ldg(&edst[base + 3]) : d4.z;
        }
        int dm1 = __shfl_up_sync(0xffffffffu, d4.w, 1);
        if ((tid & 31) == 0)
            dm1 = (base == 0) ? -1 : __ldg(&edst[base - 1]);

        if (d4.x > dm1)  for (int n = dm1 + 1;  n <= d4.x; n++) g_seg[n] = base;
        if (base + 1 < E && d4.y > d4.x) for (int n = d4.x + 1; n <= d4.y; n++) g_seg[n] = base + 1;
        if (base + 2 < E && d4.z > d4.y) for (int n = d4.y + 1; n <= d4.z; n++) g_seg[n] = base + 2;
        if (base + 3 < E && d4.w > d4.z) for (int n = d4.z + 1; n <= d4.w; n++) g_seg[n] = base + 3;
        if (base + 4 >= E) {
            for (int n = d4.w + 1; n <= N; n++) g_seg[n] = E;
        }
    }
}

// ---------------------------------------------------------------------------
// Kernel 1: bf16-split tensor GEMM (round-13 winner, unchanged).
// ---------------------------------------------------------------------------
static const uint32_t A_HI = 0;
static const uint32_t A_LO = 34816;
static const uint32_t B_HI = 69632;
static const uint32_t B_LO = 104448;
static const uint32_t SC_AW = 139264;
static const uint32_t SC_B  = 140288;
static const uint32_t S_PD  = 140800;
static const uint32_t S_PS  = 142848;
static const uint32_t GEMM_SMEM = 144896;

__global__ void __launch_bounds__(512, 1)
gat_gemm_mma_kernel(const float* __restrict__ x, const float* __restrict__ W,
                    const float* __restrict__ b, const float* __restrict__ aw,
                    const int* __restrict__ edst,
                    int N, int E, int gemm_blocks) {
    if ((int)blockIdx.x >= gemm_blocks) {
        seg_build(edst, N, E, blockIdx.x - gemm_blocks);
        return;
    }

    extern __shared__ char smem[];
    const uint32_t sb = smem_u32(smem);
    const int tid = threadIdx.x, wid = tid >> 5, lane = tid & 31;
    const int warp_m = wid >> 2, warp_n = wid & 3;
    const int m0 = warp_m * 32, n0 = warp_n * 32;
    const int row0 = blockIdx.x * 128;

    if (tid < 256) ((float*)(smem + SC_AW))[tid] = aw[tid];
    else if (tid < 384) ((float*)(smem + SC_B))[tid - 256] = b[tid - 256];

#pragma unroll
    for (int i = 0; i < 8; i++) {
        int j = tid + i * 512;
        int k = j >> 5;
        int n = (j & 31) * 4;
        float4 v = *(const float4*)&W[(size_t)k * 128 + n];
        __nv_bfloat162 h01 = __floats2bfloat162_rn(v.x, v.y);
        __nv_bfloat162 h23 = __floats2bfloat162_rn(v.z, v.w);
        float l0 = v.x - __bfloat162float(h01.x);
        float l1 = v.y - __bfloat162float(h01.y);
        float l2 = v.z - __bfloat162float(h23.x);
        float l3 = v.w - __bfloat162float(h23.y);
        __nv_bfloat162 lo01 = __floats2bfloat162_rn(l0, l1);
        __nv_bfloat162 lo23 = __floats2bfloat162_rn(l2, l3);
        uint32_t off = (uint32_t)(k * LDA + n) * 2;
        *(uint2*)(smem + B_HI + off) = make_uint2(*(uint32_t*)&h01, *(uint32_t*)&h23);
        *(uint2*)(smem + B_LO + off) = make_uint2(*(uint32_t*)&lo01, *(uint32_t*)&lo23);
    }

#pragma unroll
    for (int i = 0; i < 8; i++) {
        int j = tid + i * 512;
        int row = j >> 5;
        int c = (j & 31) * 4;
        float4 v = make_float4(0.f, 0.f, 0.f, 0.f);
        int gr = row0 + row;
        if (gr < N) v = *(const float4*)&x[(size_t)gr * 128 + c];
        __nv_bfloat162 h01 = __floats2bfloat162_rn(v.x, v.y);
        __nv_bfloat162 h23 = __floats2bfloat162_rn(v.z, v.w);
        float l0 = v.x - __bfloat162float(h01.x);
        float l1 = v.y - __bfloat162float(h01.y);
        float l2 = v.z - __bfloat162float(h23.x);
        float l3 = v.w - __bfloat162float(h23.y);
        __nv_bfloat162 lo01 = __floats2bfloat162_rn(l0, l1);
        __nv_bfloat162 lo23 = __floats2bfloat162_rn(l2, l3);
        uint32_t off = (uint32_t)(row * LDA + c) * 2;
        *(uint2*)(smem + A_HI + off) = make_uint2(*(uint32_t*)&h01, *(uint32_t*)&h23);
        *(uint2*)(smem + A_LO + off) = make_uint2(*(uint32_t*)&lo01, *(uint32_t*)&lo23);
    }
    __syncthreads();

    float acc[2][4][4];
#pragma unroll
    for (int mb = 0; mb < 2; mb++)
#pragma unroll
        for (int nb = 0; nb < 4; nb++)
#pragma unroll
            for (int q = 0; q < 4; q++) acc[mb][nb][q] = 0.f;

    const int a_row = lane & 15, a_half = (lane >> 4) * 8;

#pragma unroll
    for (int ks = 0; ks < 8; ks++) {
        int k0 = ks * 16;
        uint32_t ahi[2][4], alo[2][4], bhi[4][2], blo[4][2];
#pragma unroll
        for (int mb = 0; mb < 2; mb++) {
            uint32_t aoff = (uint32_t)((m0 + mb * 16 + a_row) * LDA + k0 + a_half) * 2;
            ldsm_x4(ahi[mb], sb + A_HI + aoff);
            ldsm_x4(alo[mb], sb + A_LO + aoff);
        }
#pragma unroll
        for (int p = 0; p < 2; p++) {
            uint32_t boff =
                (uint32_t)((k0 + a_row) * LDA + n0 + p * 16 + a_half) * 2;
            uint32_t r[4];
            ldsm_x4_trans(r, sb + B_HI + boff);
            bhi[2 * p][0] = r[0]; bhi[2 * p][1] = r[1];
            bhi[2 * p + 1][0] = r[2]; bhi[2 * p + 1][1] = r[3];
            ldsm_x4_trans(r, sb + B_LO + boff);
            blo[2 * p][0] = r[0]; blo[2 * p][1] = r[1];
            blo[2 * p + 1][0] = r[2]; blo[2 * p + 1][1] = r[3];
        }
#pragma unroll
        for (int mb = 0; mb < 2; mb++)
#pragma unroll
            for (int nb = 0; nb < 4; nb++)
                mma_bf16(acc[mb][nb], ahi[mb], bhi[nb]);
#pragma unroll
        for (int mb = 0; mb < 2; mb++)
#pragma unroll
            for (int nb = 0; nb < 4; nb++)
                mma_bf16(acc[mb][nb], ahi[mb], blo[nb]);
#pragma unroll
        for (int mb = 0; mb < 2; mb++)
#pragma unroll
            for (int nb = 0; nb < 4; nb++)
                mma_bf16(acc[mb][nb], alo[mb], bhi[nb]);
    }

    const float* s_awd = (const float*)(smem + SC_AW);
    const float* s_aws = s_awd + 128;
    const float* s_bb  = (const float*)(smem + SC_B);
    float pd4[4] = {0.f, 0.f, 0.f, 0.f};
    float ps4[4] = {0.f, 0.f, 0.f, 0.f};

#pragma unroll
    for (int mb = 0; mb < 2; mb++) {
        int gr0 = row0 + m0 + mb * 16 + (lane >> 2);
        int gr1 = gr0 + 8;
#pragma unroll
        for (int nb = 0; nb < 4; nb++) {
            int col = n0 + nb * 8 + (lane & 3) * 2;
            float bc0 = s_bb[col], bc1 = s_bb[col + 1];
            float v00 = acc[mb][nb][0] + bc0;
            float v01 = acc[mb][nb][1] + bc1;
            float v10 = acc[mb][nb][2] + bc0;
            float v11 = acc[mb][nb][3] + bc1;
            float ad0 = s_awd[col], ad1 = s_awd[col + 1];
            float as0 = s_aws[col], as1 = s_aws[col + 1];
            pd4[mb * 2 + 0] = fmaf(v00, ad0, fmaf(v01, ad1, pd4[mb * 2 + 0]));
            pd4[mb * 2 + 1] = fmaf(v10, ad0, fmaf(v11, ad1, pd4[mb * 2 + 1]));
            ps4[mb * 2 + 0] = fmaf(v00, as0, fmaf(v01, as1, ps4[mb * 2 + 0]));
            ps4[mb * 2 + 1] = fmaf(v10, as0, fmaf(v11, as1, ps4[mb * 2 + 1]));
            if (gr0 < N) {
                __half2 hp = __floats2half2_rn(v00, v01);
                *(uint32_t*)&g_hh[(size_t)gr0 * 128 + col] = *(uint32_t*)&hp;
            }
            if (gr1 < N) {
                __half2 hp = __floats2half2_rn(v10, v11);
                *(uint32_t*)&g_hh[(size_t)gr1 * 128 + col] = *(uint32_t*)&hp;
            }
        }
    }

#pragma unroll
    for (int q = 0; q < 4; q++) {
        pd4[q] += __shfl_xor_sync(0xffffffffu, pd4[q], 1);
        pd4[q] += __shfl_xor_sync(0xffffffffu, pd4[q], 2);
        ps4[q] += __shfl_xor_sync(0xffffffffu, ps4[q], 1);
        ps4[q] += __shfl_xor_sync(0xffffffffu, ps4[q], 2);
    }
    float* sPD = (float*)(smem + S_PD);
    float* sPS = (float*)(smem + S_PS);
    if ((lane & 3) == 0) {
#pragma unroll
        for (int q = 0; q < 4; q++) {
            int r = m0 + (q >> 1) * 16 + (q & 1) * 8 + (lane >> 2);
            sPD[warp_n * 128 + r] = pd4[q];
            sPS[warp_n * 128 + r] = ps4[q];
        }
    }
    __syncthreads();
    if (tid < 128) {
        int gr = row0 + tid;
        if (gr < N) {
            g_sdst[gr] = (sPD[tid] + sPD[128 + tid]) + (sPD[256 + tid] + sPD[384 + tid]);
            g_ssrc[gr] = (sPS[tid] + sPS[128 + tid]) + (sPS[256 + tid] + sPS[384 + tid]);
        }
    }
}

// ---------------------------------------------------------------------------
// Agg helper: generic chunked path for one node (deg > 32 fallback).
// ---------------------------------------------------------------------------
__device__ __forceinline__ void agg_one(const int* __restrict__ esrc,
                                        int ss, int ee, float sdn, float ab,
                                        float2* wb, int lane,
                                        float4& acc, float& denom) {
    const char* hbase = (const char*)g_hh + lane * 8;
    for (int base = ss; base < ee; base += 32) {
        int e = base + lane;
        int off = 0;
        float w = 0.f;
        if (e < ee) {
            int src = __ldg(&esrc[e]);
            float l = sdn + __ldg(&g_ssrc[src]) + ab;
            l = (l >= 0.f) ? l : 0.01f * l;
            w = __expf(l);
            denom += w;
            off = src << 8;
        }
        __syncwarp();
        wb[lane] = make_float2(w, __int_as_float(off));
        __syncwarp();
        int cnt = min(32, ee - base);
#pragma unroll 4
        for (int j = 0; j < cnt; j++) {
            float2 p = wb[j];
            uint2 u = *(const uint2*)(hbase + __float_as_int(p.y));
            float2 f0 = __half22float2(*(__half2*)&u.x);
            float2 f1 = __half22float2(*(__half2*)&u.y);
            acc.x = fmaf(p.x, f0.x, acc.x);
            acc.y = fmaf(p.x, f0.y, acc.y);
            acc.z = fmaf(p.x, f1.x, acc.z);
            acc.w = fmaf(p.x, f1.y, acc.w);
        }
        __syncwarp();
    }
}

// ---------------------------------------------------------------------------
// Kernel 2: softmax + aggregation, TWO adjacent nodes per warp.
// Fused j-loop over max(d0,d1) with 2 independent gather chains per trip.
// No max subtraction (logits O(1); exp(l)/sum exp(l) exact).
// ---------------------------------------------------------------------------
__global__ void __launch_bounds__(256)
gat_agg_kernel(const int* __restrict__ esrc,
               const float* __restrict__ abp, float* __restrict__ out, int N) {
    __shared__ float2 wbuf_all[8][64];   // per warp: [0..31] node0, [32..63] node1

    const int warp = threadIdx.x >> 5;
    const int lane = threadIdx.x & 31;
    const int n0 = (blockIdx.x * 8 + warp) * 2;
    if (n0 >= N) return;
    const int n1 = n0 + 1;
    const bool has1 = (n1 < N);
    const float ab = __ldg(abp);

    const int s0 = __ldg(&g_seg[n0]);
    const int e0 = __ldg(&g_seg[n0 + 1]);
    const int e1 = has1 ? __ldg(&g_seg[n0 + 2]) : e0;
    const int d0 = e0 - s0, d1 = e1 - e0;

    const float sdn0 = __ldg(&g_sdst[n0]);
    const float sdn1 = has1 ? __ldg(&g_sdst[n1]) : 0.f;
    float2* wbuf = wbuf_all[warp];
    const char* hbase = (const char*)g_hh + lane * 8;

    float4 acc0 = make_float4(0.f, 0.f, 0.f, 0.f);
    float4 acc1 = make_float4(0.f, 0.f, 0.f, 0.f);
    float denom0 = 0.f, denom1 = 0.f;

    if (d0 <= 32 && d1 <= 32) {
        // Fast path: both prefixes concurrently, fused interleaved j-loop.
        int eA = s0 + lane;
        int off0 = 0;
        float w0 = 0.f;
        if (eA < e0) {
            int src = __ldg(&esrc[eA]);
            float l = sdn0 + __ldg(&g_ssrc[src]) + ab;
            l = (l >= 0.f) ? l : 0.01f * l;
            w0 = __expf(l);
            off0 = src << 8;
        }
        int eB = e0 + lane;
        int off1 = 0;
        float w1 = 0.f;
        if (eB < e1) {
            int src = __ldg(&esrc[eB]);
            float l = sdn1 + __ldg(&g_ssrc[src]) + ab;
            l = (l >= 0.f) ? l : 0.01f * l;
            w1 = __expf(l);
            off1 = src << 8;
        }
        denom0 = w0;
        denom1 = w1;
        wbuf[lane]      = make_float2(w0, __int_as_float(off0));
        wbuf[32 + lane] = make_float2(w1, __int_as_float(off1));
        __syncwarp();

        int dmax = max(d0, d1);
#pragma unroll 4
        for (int j = 0; j < dmax; j++) {
            if (j < d0) {
                float2 p = wbuf[j];
                uint2 u = *(const uint2*)(hbase + __float_as_int(p.y));
                float2 f0 = __half22float2(*(__half2*)&u.x);
                float2 f1 = __half22float2(*(__half2*)&u.y);
                acc0.x = fmaf(p.x, f0.x, acc0.x);
                acc0.y = fmaf(p.x, f0.y, acc0.y);
                acc0.z = fmaf(p.x, f1.x, acc0.z);
                acc0.w = fmaf(p.x, f1.y, acc0.w);
            }
            if (j < d1) {
                float2 p = wbuf[32 + j];
                uint2 u = *(const uint2*)(hbase + __float_as_int(p.y));
                float2 f0 = __half22float2(*(__half2*)&u.x);
                float2 f1 = __half22float2(*(__half2*)&u.y);
                acc1.x = fmaf(p.x, f0.x, acc1.x);
                acc1.y = fmaf(p.x, f0.y, acc1.y);
                acc1.z = fmaf(p.x, f1.x, acc1.z);
                acc1.w = fmaf(p.x, f1.y, acc1.w);
            }
        }
    } else {
        agg_one(esrc, s0, e0, sdn0, ab, wbuf, lane, acc0, denom0);
        if (has1)
            agg_one(esrc, e0, e1, sdn1, ab, wbuf, lane, acc1, denom1);
    }

#pragma unroll
    for (int off = 16; off; off >>= 1) {
        denom0 += __shfl_xor_sync(0xffffffffu, denom0, off);
        denom1 += __shfl_xor_sync(0xffffffffu, denom1, off);
    }
    float inv0 = (denom0 > 0.f) ? (1.f / denom0) : 0.f;
    float inv1 = (denom1 > 0.f) ? (1.f / denom1) : 0.f;
    acc0.x *= inv0; acc0.y *= inv0; acc0.z *= inv0; acc0.w *= inv0;
    acc1.x *= inv1; acc1.y *= inv1; acc1.z *= inv1; acc1.w *= inv1;
    *(float4*)&out[(size_t)n0 * 128 + lane * 4] = acc0;
    if (has1)
        *(float4*)&out[(size_t)n1 * 128 + lane * 4] = acc1;
}

// ---------------------------------------------------------------------------
extern "C" void kernel_launch(void* const* d_in, const int* in_sizes, int n_in,
                              void* d_out, int out_size) {
    const float* x    = (const float*)d_in[0];
    const int*   esrc = (const int*)d_in[1];
    const int*   edst = (const int*)d_in[2];
    const float* W    = (const float*)d_in[3];
    const float* b    = (const float*)d_in[4];
    const float* aw   = (const float*)d_in[5];
    const float* ab   = (const float*)d_in[6];
    float* out = (float*)d_out;

    const int N = in_sizes[0] / DOUT;
    const int E = in_sizes[1];

    cudaFuncSetAttribute(gat_gemm_mma_kernel,
                         cudaFuncAttributeMaxDynamicSharedMemorySize, GEMM_SMEM);
    int gemm_blocks = (N + 127) / 128;
    gat_gemm_mma_kernel<<<gemm_blocks + SEG_BLOCKS, 512, GEMM_SMEM>>>(
        x, W, b, aw, edst, N, E, gemm_blocks);

    int npairs = (N + 1) / 2;
    int agg_blocks = (npairs + 7) / 8;
    gat_agg_kernel<<<agg_blocks, 256>>>(esrc, ab, out, N);
}